// round 11
// baseline (speedup 1.0000x reference)
#include <cuda_runtime.h>

// CharAttention: B=512, W=128, c=24, C=32, H=2, D=16.
// Only the row at x_end_idx is needed -> one causal attention row per (b,w)
// tile with folded weights:
//   M_h = W_q_h @ W_k_h^T / sqrt(D)   (score_h(k) = x_q M_h x_k^T)
//   P_h = W_v_h @ W_proj[h*D:(h+1)*D] (y = sum_h (sum_k att_hk x_k) P_h)
// out = x[idx] + y.
// R3/R6: warp-pair per tile + pipeline + no-max softmax.        [67.5 us]
// R7 (2-acc) NEUTRAL, R8 (key-split) REGR, R9 (branch-free s) NEUTRAL:
//   stuck at the L1 port wall — pair layout pays tile traffic TWICE.
// R10: ONE warp per tile, BOTH heads per warp: halves score-row reads,
//   s-column reads, and all broadcast round-trips; zero bar.sync (syncwarp
//   only). 128 weight regs/thread; prefetch is direct LDG->STS (no live
//   register staging); launch_bounds(128,3) caps regs at 170 -> 12 warps/SM.

#define NTILES (512 * 128)
#define CBLK 24
#define EMB 32
#define XSTRIDE 36      // pad (mult of 4, %32==4): conflict-free float4-row AND scalar-column
#define WARPS_PER_BLK 4
#define THREADS 128
#define GRID 444        // 3 blocks/SM * 148 SMs
#define WSTRIDE (GRID * WARPS_PER_BLK)

__device__ float g_M[2 * 32 * 32];  // [h][i][j]
__device__ float g_P[2 * 32 * 32];  // [h][i][j]

__global__ void precompute_kernel(const float* __restrict__ w_attn,
                                  const float* __restrict__ w_proj) {
    int t = blockIdx.x * blockDim.x + threadIdx.x;
    if (t >= 4096) return;
    int which = t >> 11;   // 0 = M, 1 = P
    int r = t & 2047;
    int h = r >> 10;
    int i = (r >> 5) & 31;
    int j = r & 31;
    float acc = 0.f;
    if (which == 0) {
        #pragma unroll
        for (int d = 0; d < 16; d++)
            acc += w_attn[i * 96 + h * 16 + d] * w_attn[j * 96 + 32 + h * 16 + d];
        g_M[r] = acc * 0.25f;  // 1/sqrt(16)
    } else {
        #pragma unroll
        for (int d = 0; d < 16; d++)
            acc += w_attn[i * 96 + 64 + h * 16 + d] * w_proj[(h * 16 + d) * 32 + j];
        g_P[r] = acc;
    }
}

__global__ void __launch_bounds__(THREADS, 3)
attn_kernel(const float* __restrict__ x, const int* __restrict__ endidx,
            float* __restrict__ out) {
    __shared__ __align__(16) float  xs[2][WARPS_PER_BLK][CBLK][XSTRIDE];
    __shared__ __align__(16) float2 us2[WARPS_PER_BLK][32];  // (u0_j, u1_j)
    __shared__ __align__(16) float2 ss2[WARPS_PER_BLK][32];  // (s0_i, s1_i)
    __shared__ __align__(16) float2 at2[WARPS_PER_BLK][32];  // (e0_r, e1_r)

    const int w    = threadIdx.x >> 5;
    const int lane = threadIdx.x & 31;

    // Both heads' folded-weight columns in registers (lane = output dim j).
    float M0[32], M1[32], P0[32], P1[32];
    #pragma unroll
    for (int i = 0; i < 32; i++) {
        M0[i] = g_M[i * 32 + lane];
        M1[i] = g_M[1024 + i * 32 + lane];
        P0[i] = g_P[i * 32 + lane];
        P1[i] = g_P[1024 + i * 32 + lane];
    }

    int bw  = blockIdx.x * WARPS_PER_BLK + w;
    int id  = __ldg(endidx + bw);
    int bw1 = bw + WSTRIDE;
    int id1 = (bw1 < NTILES) ? __ldg(endidx + bw1) : 0;

    // ---- Prologue: stage tile n directly LDG->STS (rows 0..id only).
    {
        const float* xt = x + (size_t)bw * (CBLK * EMB);
        const int totalF = (id + 1) * EMB;
        #pragma unroll
        for (int k = 0; k < 6; k++) {
            int e = lane * 4 + k * 128;
            if (e < totalF)
                *reinterpret_cast<float4*>(&xs[0][w][e >> 5][e & 31]) =
                    *reinterpret_cast<const float4*>(xt + e);
        }
    }
    __syncwarp();

    int buf = 0;
    while (bw < NTILES) {
        // ---- Prefetch: idx n+2; tile n+1 direct LDG->STS into idle buffer.
        //      (transient regs only; STS drains behind this tile's compute)
        const int bw2 = bw1 + WSTRIDE;
        const int id2 = (bw2 < NTILES) ? __ldg(endidx + bw2) : 0;
        if (bw1 < NTILES) {
            const float* xt = x + (size_t)bw1 * (CBLK * EMB);
            const int totalF = (id1 + 1) * EMB;
            #pragma unroll
            for (int k = 0; k < 6; k++) {
                int e = lane * 4 + k * 128;
                if (e < totalF)
                    *reinterpret_cast<float4*>(&xs[buf ^ 1][w][e >> 5][e & 31]) =
                        *reinterpret_cast<const float4*>(xt + e);
            }
        }

        const int nk = id + 1;

        // ---- q: residual value (column read) + broadcast row reads for u.
        const float qv = xs[buf][w][id][lane];
        const float4* qr = reinterpret_cast<const float4*>(&xs[buf][w][id][0]);

        // ---- u_h = q @ M_h  (lane = output dim j), both heads, 2 accs each.
        float u0a = 0.f, u0b = 0.f, u1a = 0.f, u1b = 0.f;
        #pragma unroll
        for (int i4 = 0; i4 < 8; i4 += 2) {
            const float4 qa = qr[i4];
            const int i = i4 * 4;
            u0a = fmaf(qa.x, M0[i + 0], u0a);  u1a = fmaf(qa.x, M1[i + 0], u1a);
            u0a = fmaf(qa.y, M0[i + 1], u0a);  u1a = fmaf(qa.y, M1[i + 1], u1a);
            u0a = fmaf(qa.z, M0[i + 2], u0a);  u1a = fmaf(qa.z, M1[i + 2], u1a);
            u0a = fmaf(qa.w, M0[i + 3], u0a);  u1a = fmaf(qa.w, M1[i + 3], u1a);
            const float4 qb = qr[i4 + 1];
            u0b = fmaf(qb.x, M0[i + 4], u0b);  u1b = fmaf(qb.x, M1[i + 4], u1b);
            u0b = fmaf(qb.y, M0[i + 5], u0b);  u1b = fmaf(qb.y, M1[i + 5], u1b);
            u0b = fmaf(qb.z, M0[i + 6], u0b);  u1b = fmaf(qb.z, M1[i + 6], u1b);
            u0b = fmaf(qb.w, M0[i + 7], u0b);  u1b = fmaf(qb.w, M1[i + 7], u1b);
        }
        us2[w][lane] = make_float2(u0a + u0b, u1a + u1b);
        __syncwarp();

        // ---- scores: lane = key r; both heads from interleaved u pairs.
        float e0 = 0.f, e1 = 0.f;
        if (lane < nk) {
            const float4* xr = reinterpret_cast<const float4*>(&xs[buf][w][lane][0]);
            const float4* uu = reinterpret_cast<const float4*>(&us2[w][0]);
            float a0 = 0.f, a1 = 0.f, b0 = 0.f, b1 = 0.f;
            #pragma unroll
            for (int i4 = 0; i4 < 8; i4++) {
                const float4 xv  = xr[i4];
                const float4 up0 = uu[2 * i4];      // (u0,u1) dims 4i4, 4i4+1
                const float4 up1 = uu[2 * i4 + 1];  // (u0,u1) dims 4i4+2, 4i4+3
                a0 = fmaf(up0.x, xv.x, a0);  b0 = fmaf(up0.y, xv.x, b0);
                a1 = fmaf(up0.z, xv.y, a1);  b1 = fmaf(up0.w, xv.y, b1);
                a0 = fmaf(up1.x, xv.z, a0);  b0 = fmaf(up1.y, xv.z, b0);
                a1 = fmaf(up1.z, xv.w, a1);  b1 = fmaf(up1.w, xv.w, b1);
            }
            // No max-shift: std(sc)=4, overflow needs sc>88 (22 sigma) — safe.
            e0 = __expf(a0 + a1);
            e1 = __expf(b0 + b1);
        }
        at2[w][lane] = make_float2(e0, e1);
        __syncwarp();

        // ---- softmax sums (both heads); overlaps the s-phase below.
        float s0 = e0, s1 = e1;
        #pragma unroll
        for (int o = 16; o > 0; o >>= 1) {
            s0 += __shfl_xor_sync(0xffffffffu, s0, o);
            s1 += __shfl_xor_sync(0xffffffffu, s1, o);
        }

        // ---- s_h = sum_r att_hr * x_r  (lane = dim i), both heads.
        float pa0 = 0.f, pa1 = 0.f;
        for (int r = 0; r < nk; r++) {
            const float2 at = at2[w][r];           // 8B broadcast
            const float xv = xs[buf][w][r][lane];  // column, conflict-free
            pa0 = fmaf(at.x, xv, pa0);
            pa1 = fmaf(at.y, xv, pa1);
        }
        pa0 = __fdividef(pa0, s0);
        pa1 = __fdividef(pa1, s1);
        ss2[w][lane] = make_float2(pa0, pa1);
        __syncwarp();

        // ---- y = s0 @ P0 + s1 @ P1  (lane = output dim j).
        const float4* sv = reinterpret_cast<const float4*>(&ss2[w][0]);
        float y0a = 0.f, y0b = 0.f, y1a = 0.f, y1b = 0.f;
        #pragma unroll
        for (int i4 = 0; i4 < 8; i4++) {
            const float4 sp0 = sv[2 * i4];      // (s0,s1) dims 4i4, 4i4+1
            const float4 sp1 = sv[2 * i4 + 1];  // (s0,s1) dims 4i4+2, 4i4+3
            const int i = i4 * 4;
            y0a = fmaf(sp0.x, P0[i + 0], y0a);  y1a = fmaf(sp0.y, P1[i + 0], y1a);
            y0a = fmaf(sp0.z, P0[i + 1], y0a);  y1a = fmaf(sp0.w, P1[i + 1], y1a);
            y0b = fmaf(sp1.x, P0[i + 2], y0b);  y1b = fmaf(sp1.y, P1[i + 2], y1b);
            y0b = fmaf(sp1.z, P0[i + 3], y0b);  y1b = fmaf(sp1.w, P1[i + 3], y1b);
        }
        out[bw * EMB + lane] = qv + (y0a + y0b) + (y1a + y1b);

        bw = bw1; id = id1;
        bw1 = bw2; id1 = id2;
        buf ^= 1;
        __syncwarp();   // orders prefetch STS vs next iteration's reads
    }
}

extern "C" void kernel_launch(void* const* d_in, const int* in_sizes, int n_in,
                              void* d_out, int out_size) {
    const float* x      = (const float*)d_in[0];
    const int*   endidx = (const int*)d_in[1];
    const float* w_attn = (const float*)d_in[2];
    const float* w_proj = (const float*)d_in[3];
    float* out = (float*)d_out;

    precompute_kernel<<<16, 256>>>(w_attn, w_proj);
    attn_kernel<<<GRID, THREADS>>>(x, endidx, out);
}